// round 10
// baseline (speedup 1.0000x reference)
#include <cuda_runtime.h>
#include <cuda_fp16.h>
#include <stdint.h>

// ---------------- problem constants ----------------
#define HID     2048
#define BATCHN  64
#define G4      8192
#define NSTEPS  30
#define NTILE   128           // M tiles of 64 gate-rows -> 128 CTAs (persistent, wave-1)
#define NKCH    32            // K chunks of 64 fp16 (128B rows, SW128)
#define WCH     8192          // bytes per W chunk tile (64 rows x 128B)
#define HCH     8192          // bytes per h chunk tile (64 batch x 128B)
#define NITER   16            // 2 chunks per iteration
#define STG     32768         // stage = 2 x (W 8K + h 8K)
#define NSTG    4
#define SMX_BYTES (4*64*17*4) // 17408
#define SMEM_REQ (NSTG*STG + SMX_BYTES + 1024)

// ---------------- device scratch (static, no allocs) ----------------
__device__ __align__(1024) unsigned char g_wsum[NTILE*NKCH*WCH]; // 32MB fp16 (Wih+Whh)
__device__ __align__(1024) unsigned char g_whh [NTILE*NKCH*WCH]; // 32MB fp16 (Whh, step 0)
__device__ __align__(1024) unsigned char g_hA[NKCH*HCH];         // 256KB tiled fp16 h
__device__ __align__(1024) unsigned char g_hB[NKCH*HCH];
__device__ float g_c[BATCHN*HID];
__device__ float g_bias[G4];
__device__ unsigned g_barrier;

// ---------------- helpers ----------------
__device__ __forceinline__ uint32_t smem_u32(const void* p) {
    uint32_t a;
    asm("{ .reg .u64 t; cvta.to.shared.u64 t, %1; cvt.u32.u64 %0, t; }" : "=r"(a) : "l"(p));
    return a;
}
__device__ __forceinline__ uint32_t swz(uint32_t o) { return o ^ ((o >> 3) & 0x70); }

__device__ __forceinline__ void ldm4(uint32_t* r, uint32_t a) {
    asm volatile("ldmatrix.sync.aligned.m8n8.x4.shared.b16 {%0,%1,%2,%3}, [%4];"
                 : "=r"(r[0]), "=r"(r[1]), "=r"(r[2]), "=r"(r[3]) : "r"(a));
}
__device__ __forceinline__ void mma16816(float* d, const uint32_t* a, uint32_t b0, uint32_t b1) {
    asm volatile("mma.sync.aligned.m16n8k16.row.col.f32.f16.f16.f32 "
                 "{%0,%1,%2,%3}, {%4,%5,%6,%7}, {%8,%9}, {%0,%1,%2,%3};"
                 : "+f"(d[0]), "+f"(d[1]), "+f"(d[2]), "+f"(d[3])
                 : "r"(a[0]), "r"(a[1]), "r"(a[2]), "r"(a[3]), "r"(b0), "r"(b1));
}
__device__ __forceinline__ void cp16(uint32_t dst, const void* src) {
    asm volatile("cp.async.cg.shared.global [%0], [%1], 16;" :: "r"(dst), "l"(src) : "memory");
}
#define CP_COMMIT() asm volatile("cp.async.commit_group;" ::: "memory")
__device__ __forceinline__ float sigm(float x) {
    x = fminf(15.f, fmaxf(-15.f, x));
    return 1.f / (1.f + __expf(-x));
}
__device__ __forceinline__ float tanh_(float x) {
    x = fminf(8.f, fmaxf(-8.f, x));
    float e = __expf(-2.f * x);
    return (1.f - e) / (1.f + e);
}

// ---------------- prep: tiled + SW128-swizzled fp16 weights ----------------
// Tile t (0..127), row r (0..63): gate = r>>4, unit = r&15 -> orig row gate*HID + t*16 + unit.
__global__ void prep_weights(const float* __restrict__ Wih, const float* __restrict__ Whh) {
    int id  = blockIdx.x * 256 + threadIdx.x;     // 8,388,608 (one half2 each)
    int cp  = id & 31;
    int row = (id >> 5) & 63;
    int kc  = (id >> 11) & 31;
    int t   = id >> 16;
    int gate = row >> 4, u = row & 15;
    long orow = (long)gate * HID + t * 16 + u;
    int  ocol = kc * 64 + cp * 2;
    float2 wi = *(const float2*)(Wih + orow * HID + ocol);
    float2 wh = *(const float2*)(Whh + orow * HID + ocol);
    uint32_t toff = (uint32_t)(t * NKCH + kc) * WCH + swz((uint32_t)(row * 128 + cp * 4));
    *(__half2*)(g_wsum + toff) =
        __halves2half2(__float2half_rn(wi.x + wh.x), __float2half_rn(wi.y + wh.y));
    *(__half2*)(g_whh + toff) =
        __halves2half2(__float2half_rn(wh.x), __float2half_rn(wh.y));
}

// zero c + barrier, fused bias, tiled fp16 h0, init out to b_out
__global__ void prep_misc(const float* __restrict__ tok,
                          const float* __restrict__ bih, const float* __restrict__ bhh,
                          const float* __restrict__ bout, float* __restrict__ out) {
    int id = blockIdx.x * 256 + threadIdx.x;      // 131072
    float h0 = tok[id];
    g_c[id] = 0.0f;
    int b = id >> 11, hid = id & 2047;
    int kc = hid >> 6, cc = hid & 63;
    uint32_t off = (uint32_t)kc * HCH + swz((uint32_t)(b * 128 + cc * 2));
    *(__half*)(g_hA + off) = __float2half_rn(h0);
    if (id < G4) g_bias[id] = bih[id] + bhh[id];
    if (id < BATCHN * NSTEPS) out[id] = bout[0];
    if (id == 0) g_barrier = 0u;
}

// ---------------- persistent kernel: all 30 steps ----------------
// 512 threads, warp grid 2M x 2N x 4K; 2 chunks per iteration, 4 stages.
#define SMX(g, b, u) smx[((g) * 64 + (b)) * 17 + (u)]

__global__ void __launch_bounds__(512, 1) lstm_persist(const float* __restrict__ Wout,
                                                       float* __restrict__ out) {
    extern __shared__ unsigned char smraw[];
    uint32_t sbr  = smem_u32(smraw);
    uint32_t base = (sbr + 1023) & ~1023u;
    float* smx = (float*)(smraw + (base - sbr) + NSTG * STG);   // separate scratch region

    int tid = threadIdx.x;
    int lane = tid & 31, wid = tid >> 5;
    int kw     = wid & 3;
    int warp_m = (wid >> 2) & 1;
    int warp_n = wid >> 3;
    int blk = blockIdx.x;

    const unsigned char* wsum_t = g_wsum + (size_t)blk * NKCH * WCH;
    const unsigned char* whh_t  = g_whh  + (size_t)blk * NKCH * WCH;

    float wout = Wout[blk * 16 + (tid & 15)];

    // ldmatrix lane address components (k16 slice at byte offset kw*32)
    uint32_t kof    = (uint32_t)kw * 32;
    uint32_t a_colb = (uint32_t)((lane >> 4) << 4);
    uint32_t a_r0   = (uint32_t)(warp_m * 32 + (lane & 15));
    uint32_t b_row  = (uint32_t)(warp_n * 32 + (lane & 7) + ((lane >> 4) << 3));
    uint32_t b_colb = (uint32_t)(((lane >> 3) & 1) << 4);

    int o = tid * 16;

    // step-0 prologue: combined W+h prefetch, stages 0..2
    #pragma unroll
    for (int s = 0; s < 3; s++) {
        uint32_t sb = base + (uint32_t)s * STG;
        size_t gw = (size_t)(2 * s) * WCH;
        size_t gh = (size_t)(2 * s) * HCH;
        cp16(sb + o,         whh_t + gw + o);
        cp16(sb + 8192 + o,  g_hA + gh + o);
        cp16(sb + 16384 + o, whh_t + gw + WCH + o);
        cp16(sb + 24576 + o, g_hA + gh + HCH + o);
        CP_COMMIT();
    }

    for (int step = 0; step < NSTEPS; step++) {
        const unsigned char* wsrc = step ? wsum_t : whh_t;
        const unsigned char* hsrc = (step & 1) ? g_hB : g_hA;
        unsigned char*       hout = (step & 1) ? g_hA : g_hB;

        float acc[2][16];
        #pragma unroll
        for (int i = 0; i < 2; i++)
            #pragma unroll
            for (int j = 0; j < 16; j++) acc[i][j] = 0.f;

        for (int kp = 0; kp < NITER; kp++) {
            if (kp < NITER - 2)       asm volatile("cp.async.wait_group 2;" ::: "memory");
            else if (kp == NITER - 2) asm volatile("cp.async.wait_group 1;" ::: "memory");
            else                      asm volatile("cp.async.wait_group 0;" ::: "memory");
            __syncthreads();

            int np = kp + 3;
            if (np < NITER) {
                uint32_t sb = base + (uint32_t)(np & 3) * STG;
                size_t gw = (size_t)(2 * np) * WCH;
                size_t gh = (size_t)(2 * np) * HCH;
                cp16(sb + o,         wsrc + gw + o);
                cp16(sb + 8192 + o,  hsrc + gh + o);
                cp16(sb + 16384 + o, wsrc + gw + WCH + o);
                cp16(sb + 24576 + o, hsrc + gh + HCH + o);
                CP_COMMIT();
            }

            uint32_t sb = base + (uint32_t)(kp & 3) * STG;
            uint32_t fa0[2][4], fa1[2][4], fb0[2][4], fb1[2][4];
            #pragma unroll
            for (int c = 0; c < 2; c++) {
                uint32_t sw = sb + (uint32_t)c * 16384;
                uint32_t sh = sw + 8192;
                ldm4(fa0[c], sw + swz(a_r0 * 128 + kof + a_colb));
                ldm4(fa1[c], sw + swz((a_r0 + 16) * 128 + kof + a_colb));
                ldm4(fb0[c], sh + swz(b_row * 128 + kof + b_colb));
                ldm4(fb1[c], sh + swz((b_row + 16) * 128 + kof + b_colb));
            }
            #pragma unroll
            for (int c = 0; c < 2; c++) {
                mma16816(acc[0] + 0,  fa0[c], fb0[c][0], fb0[c][1]);
                mma16816(acc[0] + 4,  fa0[c], fb0[c][2], fb0[c][3]);
                mma16816(acc[0] + 8,  fa0[c], fb1[c][0], fb1[c][1]);
                mma16816(acc[0] + 12, fa0[c], fb1[c][2], fb1[c][3]);
                mma16816(acc[1] + 0,  fa1[c], fb0[c][0], fb0[c][1]);
                mma16816(acc[1] + 4,  fa1[c], fb0[c][2], fb0[c][3]);
                mma16816(acc[1] + 8,  fa1[c], fb1[c][0], fb1[c][1]);
                mma16816(acc[1] + 12, fa1[c], fb1[c][2], fb1[c][3]);
            }
        }
        __syncthreads();

        // ---- K-group reduction into smx[gate][batch][unit] (4 sequential rounds) ----
        #pragma unroll
        for (int r = 0; r < 4; r++) {
            if (kw == r) {
                #pragma unroll
                for (int mt = 0; mt < 2; mt++) {
                    int gate = warp_m * 2 + mt;
                    #pragma unroll
                    for (int g = 0; g < 4; g++) {
                        int n0 = warp_n * 32 + 8 * g + 2 * (lane & 3);
                        int u0 = lane >> 2;
                        if (r == 0) {
                            SMX(gate, n0,     u0    ) = acc[mt][4 * g + 0];
                            SMX(gate, n0 + 1, u0    ) = acc[mt][4 * g + 1];
                            SMX(gate, n0,     u0 + 8) = acc[mt][4 * g + 2];
                            SMX(gate, n0 + 1, u0 + 8) = acc[mt][4 * g + 3];
                        } else {
                            SMX(gate, n0,     u0    ) += acc[mt][4 * g + 0];
                            SMX(gate, n0 + 1, u0    ) += acc[mt][4 * g + 1];
                            SMX(gate, n0,     u0 + 8) += acc[mt][4 * g + 2];
                            SMX(gate, n0 + 1, u0 + 8) += acc[mt][4 * g + 3];
                        }
                    }
                }
            }
            __syncthreads();
        }

        // ---- fused LSTM cell + output projection ----
        int kcb = blk >> 2;
        #pragma unroll
        for (int k = 0; k < 2; k++) {
            int p = k * 512 + tid;          // (unit, batch); u = tid&15 constant
            int u = p & 15, b = p >> 4;
            int hid = blk * 16 + u;
            float xi = SMX(0, b, u) + g_bias[hid];
            float xf = SMX(1, b, u) + g_bias[2048 + hid];
            float xg = SMX(2, b, u) + g_bias[4096 + hid];
            float xo = SMX(3, b, u) + g_bias[6144 + hid];
            float ii = sigm(xi), ff = sigm(xf), gg = tanh_(xg), oo = sigm(xo);
            int ci = b * HID + hid;
            float c = ff * g_c[ci] + ii * gg;
            g_c[ci] = c;
            float h = oo * tanh_(c);
            uint32_t off = (uint32_t)kcb * HCH +
                           swz((uint32_t)(b * 128 + ((blk & 3) * 16 + u) * 2));
            *(__half*)(hout + off) = __float2half_rn(h);
            // y partial: reduce h*wout over the 16 units in this lane group
            float part = h * wout;
            #pragma unroll
            for (int s = 8; s; s >>= 1)
                part += __shfl_xor_sync(0xFFFFFFFFu, part, s);
            if ((lane & 15) == 0)
                atomicAdd(out + b * NSTEPS + step, part);
        }

        if (step < NSTEPS - 1) {
            // W prefetch for next step (W independent of barrier), stages 0..2
            #pragma unroll
            for (int s = 0; s < 3; s++) {
                uint32_t sb = base + (uint32_t)s * STG;
                size_t gw = (size_t)(2 * s) * WCH;
                cp16(sb + o,         wsum_t + gw + o);
                cp16(sb + 16384 + o, wsum_t + gw + WCH + o);
                CP_COMMIT();
            }
            // grid barrier: h of this step visible to all CTAs
            __threadfence();
            __syncthreads();
            if (tid == 0) {
                atomicAdd(&g_barrier, 1u);
                unsigned target = 128u * (unsigned)(step + 1);
                while (*(volatile unsigned*)&g_barrier < target) __nanosleep(64);
                __threadfence();
            }
            __syncthreads();
            // h prefetch for next step (source = hout just produced), stages 0..2
            #pragma unroll
            for (int s = 0; s < 3; s++) {
                uint32_t sb = base + (uint32_t)s * STG;
                size_t gh = (size_t)(2 * s) * HCH;
                cp16(sb + 8192 + o,  hout + gh + o);
                cp16(sb + 24576 + o, hout + gh + HCH + o);
                CP_COMMIT();
            }
        }
    }
}

// ---------------- launch ----------------
extern "C" void kernel_launch(void* const* d_in, const int* in_sizes, int n_in,
                              void* d_out, int out_size) {
    int wi = (n_in >= 8) ? 2 : 1;   // skip scalar `steps` input if present
    const float* tok  = (const float*)d_in[0];
    const float* Wih  = (const float*)d_in[wi];
    const float* Whh  = (const float*)d_in[wi + 1];
    const float* bih  = (const float*)d_in[wi + 2];
    const float* bhh  = (const float*)d_in[wi + 3];
    const float* Wout = (const float*)d_in[wi + 4];
    const float* bout = (const float*)d_in[wi + 5];
    float* out = (float*)d_out;

    cudaFuncSetAttribute(lstm_persist, cudaFuncAttributeMaxDynamicSharedMemorySize, SMEM_REQ);

    prep_weights<<<32768, 256>>>(Wih, Whh);
    prep_misc<<<512, 256>>>(tok, bih, bhh, bout, out);
    lstm_persist<<<NTILE, 512, SMEM_REQ>>>(Wout, out);
}

// round 11
// speedup vs baseline: 1.0277x; 1.0277x over previous
#include <cuda_runtime.h>
#include <cuda_fp16.h>
#include <stdint.h>

// ---------------- problem constants ----------------
#define HID     2048
#define BATCHN  64
#define G4      8192
#define NSTEPS  30
#define NTILE   256           // M tiles of 32 gate-rows -> 256 CTAs (occupancy 2)
#define NKCH    32            // K chunks of 64 fp16 (128B rows, SW128)
#define WCH     4096          // bytes per W chunk tile (32 rows x 128B)
#define HCH     8192          // bytes per h chunk tile (64 batch x 128B)
#define NITER   16            // 2 chunks per iteration
#define STG     24576         // stage = 2 x (W 4K) + 2 x (h 8K)
#define NSTG    4
#define SMX_BYTES (4*64*9*4)  // 9216
#define SMEM_REQ (NSTG*STG + SMX_BYTES + 1024)   // 108544

// ---------------- device scratch (static, no allocs) ----------------
__device__ __align__(1024) unsigned char g_wsum[NTILE*NKCH*WCH]; // 32MB fp16 (Wih+Whh)
__device__ __align__(1024) unsigned char g_whh [NTILE*NKCH*WCH]; // 32MB fp16 (Whh, step 0)
__device__ __align__(1024) unsigned char g_hA[NKCH*HCH];         // 256KB tiled fp16 h
__device__ __align__(1024) unsigned char g_hB[NKCH*HCH];
__device__ float g_c[BATCHN*HID];
__device__ float g_bias[G4];
__device__ float g_hist[NSTEPS*BATCHN*HID];

// ---------------- helpers ----------------
__device__ __forceinline__ uint32_t smem_u32(const void* p) {
    uint32_t a;
    asm("{ .reg .u64 t; cvta.to.shared.u64 t, %1; cvt.u32.u64 %0, t; }" : "=r"(a) : "l"(p));
    return a;
}
__device__ __forceinline__ uint32_t swz(uint32_t o) { return o ^ ((o >> 3) & 0x70); }

__device__ __forceinline__ void ldm4(uint32_t* r, uint32_t a) {
    asm volatile("ldmatrix.sync.aligned.m8n8.x4.shared.b16 {%0,%1,%2,%3}, [%4];"
                 : "=r"(r[0]), "=r"(r[1]), "=r"(r[2]), "=r"(r[3]) : "r"(a));
}
__device__ __forceinline__ void mma16816(float* d, const uint32_t* a, uint32_t b0, uint32_t b1) {
    asm volatile("mma.sync.aligned.m16n8k16.row.col.f32.f16.f16.f32 "
                 "{%0,%1,%2,%3}, {%4,%5,%6,%7}, {%8,%9}, {%0,%1,%2,%3};"
                 : "+f"(d[0]), "+f"(d[1]), "+f"(d[2]), "+f"(d[3])
                 : "r"(a[0]), "r"(a[1]), "r"(a[2]), "r"(a[3]), "r"(b0), "r"(b1));
}
__device__ __forceinline__ void cp16(uint32_t dst, const void* src) {
    asm volatile("cp.async.cg.shared.global [%0], [%1], 16;" :: "r"(dst), "l"(src) : "memory");
}
#define CP_COMMIT() asm volatile("cp.async.commit_group;" ::: "memory")
__device__ __forceinline__ float sigm(float x) {
    x = fminf(15.f, fmaxf(-15.f, x));
    return 1.f / (1.f + __expf(-x));
}
__device__ __forceinline__ float tanh_(float x) {
    x = fminf(8.f, fmaxf(-8.f, x));
    float e = __expf(-2.f * x);
    return (1.f - e) / (1.f + e);
}

// ---------------- prep: tiled + SW128-swizzled fp16 weights ----------------
// Tile t (0..255), row r (0..31): gate = r>>3, unit = r&7 -> orig row gate*HID + t*8 + unit.
__global__ void prep_weights(const float* __restrict__ Wih, const float* __restrict__ Whh) {
    int id  = blockIdx.x * 256 + threadIdx.x;     // 8,388,608 (one half2 each)
    int cp  = id & 31;
    int row = (id >> 5) & 31;
    int kc  = (id >> 10) & 31;
    int t   = id >> 15;
    int gate = row >> 3, u = row & 7;
    long orow = (long)gate * HID + t * 8 + u;
    int  ocol = kc * 64 + cp * 2;
    float2 wi = *(const float2*)(Wih + orow * HID + ocol);
    float2 wh = *(const float2*)(Whh + orow * HID + ocol);
    uint32_t toff = (uint32_t)(t * NKCH + kc) * WCH + swz((uint32_t)(row * 128 + cp * 4));
    *(__half2*)(g_wsum + toff) =
        __halves2half2(__float2half_rn(wi.x + wh.x), __float2half_rn(wi.y + wh.y));
    *(__half2*)(g_whh + toff) =
        __halves2half2(__float2half_rn(wh.x), __float2half_rn(wh.y));
}

// zero c, fused bias, tiled fp16 h0 into buffer A
__global__ void prep_misc(const float* __restrict__ tok,
                          const float* __restrict__ bih, const float* __restrict__ bhh) {
    int id = blockIdx.x * 256 + threadIdx.x;      // 131072
    float h0 = tok[id];
    g_c[id] = 0.0f;
    int b = id >> 11, hid = id & 2047;
    int kc = hid >> 6, cc = hid & 63;
    uint32_t off = (uint32_t)kc * HCH + swz((uint32_t)(b * 128 + cc * 2));
    *(__half*)(g_hA + off) = __float2half_rn(h0);
    if (id < G4) g_bias[id] = bih[id] + bhh[id];
}

// ---------------- one LSTM step ----------------
// 256 threads, 8 warps: kw = wid&3 (k16 slice), warp_n = wid>>2 (batch half).
// Warp tile m32 x n32; CTA tile m32(= 4 gates x 8 units) x n64 x k64-chunks.
#define SMX(g, b, u) smx[((g) * 64 + (b)) * 9 + (u)]

__global__ void __launch_bounds__(256, 2) lstm_step(int step) {
    extern __shared__ unsigned char smraw[];
    uint32_t sbr  = smem_u32(smraw);
    uint32_t base = (sbr + 1023) & ~1023u;
    float* smx = (float*)(smraw + (base - sbr) + NSTG * STG);

    int tid = threadIdx.x;
    int lane = tid & 31, wid = tid >> 5;
    int kw     = wid & 3;
    int warp_n = wid >> 2;
    int blk = blockIdx.x;

    const unsigned char* wsrc = ((step ? g_wsum : g_whh) + (size_t)blk * NKCH * WCH);
    const unsigned char* hsrc = (step & 1) ? g_hB : g_hA;
    unsigned char*       hout = (step & 1) ? g_hA : g_hB;

    // ldmatrix lane address components (k16 slice at byte offset kw*32)
    uint32_t kof    = (uint32_t)kw * 32;
    uint32_t a_colb = (uint32_t)((lane >> 4) << 4);
    uint32_t a_r0   = (uint32_t)(lane & 15);
    uint32_t b_row  = (uint32_t)(warp_n * 32 + (lane & 7) + ((lane >> 4) << 3));
    uint32_t b_colb = (uint32_t)(((lane >> 3) & 1) << 4);

    float acc[2][16];
    #pragma unroll
    for (int i = 0; i < 2; i++)
        #pragma unroll
        for (int j = 0; j < 16; j++) acc[i][j] = 0.f;

    int o = tid * 16;   // 0..4080

    // prefetch stages 0..2 (chunks 0..5): per stage W 8KB contiguous + h 16KB contiguous
    #pragma unroll
    for (int s = 0; s < 3; s++) {
        uint32_t sb = base + (uint32_t)s * STG;
        size_t gw = (size_t)(2 * s) * WCH;
        size_t gh = (size_t)(2 * s) * HCH;
        cp16(sb + o,        wsrc + gw + o);
        cp16(sb + 4096 + o, wsrc + gw + 4096 + o);
        cp16(sb + 8192 + o,         hsrc + gh + o);
        cp16(sb + 8192 + 4096 + o,  hsrc + gh + 4096 + o);
        cp16(sb + 8192 + 8192 + o,  hsrc + gh + 8192 + o);
        cp16(sb + 8192 + 12288 + o, hsrc + gh + 12288 + o);
        CP_COMMIT();
    }

    for (int kp = 0; kp < NITER; kp++) {
        if (kp < NITER - 2)       asm volatile("cp.async.wait_group 2;" ::: "memory");
        else if (kp == NITER - 2) asm volatile("cp.async.wait_group 1;" ::: "memory");
        else                      asm volatile("cp.async.wait_group 0;" ::: "memory");
        __syncthreads();

        int np = kp + 3;
        if (np < NITER) {
            uint32_t sb = base + (uint32_t)(np & 3) * STG;
            size_t gw = (size_t)(2 * np) * WCH;
            size_t gh = (size_t)(2 * np) * HCH;
            cp16(sb + o,        wsrc + gw + o);
            cp16(sb + 4096 + o, wsrc + gw + 4096 + o);
            cp16(sb + 8192 + o,         hsrc + gh + o);
            cp16(sb + 8192 + 4096 + o,  hsrc + gh + 4096 + o);
            cp16(sb + 8192 + 8192 + o,  hsrc + gh + 8192 + o);
            cp16(sb + 8192 + 12288 + o, hsrc + gh + 12288 + o);
            CP_COMMIT();
        }

        uint32_t sb = base + (uint32_t)(kp & 3) * STG;
        uint32_t fa0[2][4], fa1[2][4], fb0[2][4], fb1[2][4];
        #pragma unroll
        for (int c = 0; c < 2; c++) {
            uint32_t sw = sb + (uint32_t)c * 4096;
            uint32_t sh = sb + 8192 + (uint32_t)c * 8192;
            ldm4(fa0[c], sw + swz(a_r0 * 128 + kof + a_colb));
            ldm4(fa1[c], sw + swz((a_r0 + 16) * 128 + kof + a_colb));
            ldm4(fb0[c], sh + swz(b_row * 128 + kof + b_colb));
            ldm4(fb1[c], sh + swz((b_row + 16) * 128 + kof + b_colb));
        }
        #pragma unroll
        for (int c = 0; c < 2; c++) {
            mma16816(acc[0] + 0,  fa0[c], fb0[c][0], fb0[c][1]);
            mma16816(acc[0] + 4,  fa0[c], fb0[c][2], fb0[c][3]);
            mma16816(acc[0] + 8,  fa0[c], fb1[c][0], fb1[c][1]);
            mma16816(acc[0] + 12, fa0[c], fb1[c][2], fb1[c][3]);
            mma16816(acc[1] + 0,  fa1[c], fb0[c][0], fb0[c][1]);
            mma16816(acc[1] + 4,  fa1[c], fb0[c][2], fb0[c][3]);
            mma16816(acc[1] + 8,  fa1[c], fb1[c][0], fb1[c][1]);
            mma16816(acc[1] + 12, fa1[c], fb1[c][2], fb1[c][3]);
        }
    }
    __syncthreads();

    // ---- K-group reduction into smx[gate][batch][unit] (4 sequential rounds) ----
    // fa0 rows 0..15 = gate0 (units 0-7) + gate1; fa1 rows 16..31 = gate2 + gate3.
    #pragma unroll
    for (int r = 0; r < 4; r++) {
        if (kw == r) {
            #pragma unroll
            for (int mt = 0; mt < 2; mt++) {
                #pragma unroll
                for (int g = 0; g < 4; g++) {
                    int n0 = warp_n * 32 + 8 * g + 2 * (lane & 3);
                    int u0 = lane >> 2;            // 0..7
                    if (r == 0) {
                        SMX(2 * mt,     n0,     u0) = acc[mt][4 * g + 0];
                        SMX(2 * mt,     n0 + 1, u0) = acc[mt][4 * g + 1];
                        SMX(2 * mt + 1, n0,     u0) = acc[mt][4 * g + 2];
                        SMX(2 * mt + 1, n0 + 1, u0) = acc[mt][4 * g + 3];
                    } else {
                        SMX(2 * mt,     n0,     u0) += acc[mt][4 * g + 0];
                        SMX(2 * mt,     n0 + 1, u0) += acc[mt][4 * g + 1];
                        SMX(2 * mt + 1, n0,     u0) += acc[mt][4 * g + 2];
                        SMX(2 * mt + 1, n0 + 1, u0) += acc[mt][4 * g + 3];
                    }
                }
            }
        }
        __syncthreads();
    }

    // ---- fused LSTM cell: 8 units x 64 batch per CTA ----
    #pragma unroll
    for (int k = 0; k < 2; k++) {
        int p = k * 256 + tid;          // (unit, batch)
        int u = p & 7, b = p >> 3;
        int hid = blk * 8 + u;
        float xi = SMX(0, b, u) + g_bias[hid];
        float xf = SMX(1, b, u) + g_bias[2048 + hid];
        float xg = SMX(2, b, u) + g_bias[4096 + hid];
        float xo = SMX(3, b, u) + g_bias[6144 + hid];
        float ii = sigm(xi), ff = sigm(xf), gg = tanh_(xg), oo = sigm(xo);
        int ci = b * HID + hid;
        float c = ff * g_c[ci] + ii * gg;
        g_c[ci] = c;
        float h = oo * tanh_(c);
        g_hist[((size_t)step * BATCHN + b) * HID + hid] = h;
        uint32_t off = (uint32_t)(hid >> 6) * HCH +
                       swz((uint32_t)(b * 128 + (hid & 63) * 2));
        *(__half*)(hout + off) = __float2half_rn(h);
    }
}

// ---------------- output projection: y[b,t] = hist[t,b,:] . W_out + b_out ----------------
__global__ void out_kernel(const float* __restrict__ Wout, const float* __restrict__ bout,
                           float* __restrict__ out) {
    int t = blockIdx.x / BATCHN;
    int b = blockIdx.x % BATCHN;
    const float4* h = (const float4*)(g_hist + ((size_t)t * BATCHN + b) * HID);
    const float4* w = (const float4*)Wout;
    float acc = 0.f;
    #pragma unroll
    for (int it = 0; it < 4; it++) {
        int k = it * 128 + threadIdx.x;
        float4 hv = h[k], wv = w[k];
        acc += hv.x * wv.x + hv.y * wv.y + hv.z * wv.z + hv.w * wv.w;
    }
    #pragma unroll
    for (int o = 16; o; o >>= 1) acc += __shfl_xor_sync(0xFFFFFFFFu, acc, o);
    __shared__ float ws[4];
    if ((threadIdx.x & 31) == 0) ws[threadIdx.x >> 5] = acc;
    __syncthreads();
    if (threadIdx.x == 0)
        out[b * NSTEPS + t] = ws[0] + ws[1] + ws[2] + ws[3] + bout[0];
}

// ---------------- launch ----------------
extern "C" void kernel_launch(void* const* d_in, const int* in_sizes, int n_in,
                              void* d_out, int out_size) {
    int wi = (n_in >= 8) ? 2 : 1;   // skip scalar `steps` input if present
    const float* tok  = (const float*)d_in[0];
    const float* Wih  = (const float*)d_in[wi];
    const float* Whh  = (const float*)d_in[wi + 1];
    const float* bih  = (const float*)d_in[wi + 2];
    const float* bhh  = (const float*)d_in[wi + 3];
    const float* Wout = (const float*)d_in[wi + 4];
    const float* bout = (const float*)d_in[wi + 5];
    float* out = (float*)d_out;

    cudaFuncSetAttribute(lstm_step, cudaFuncAttributeMaxDynamicSharedMemorySize, SMEM_REQ);

    prep_weights<<<32768, 256>>>(Wih, Whh);
    prep_misc<<<512, 256>>>(tok, bih, bhh);
    for (int t = 0; t < NSTEPS; t++)
        lstm_step<<<NTILE, 256, SMEM_REQ>>>(t);
    out_kernel<<<NSTEPS * BATCHN, 128>>>(Wout, bout, out);
}

// round 13
// speedup vs baseline: 1.0377x; 1.0097x over previous
#include <cuda_runtime.h>
#include <cuda_fp16.h>
#include <stdint.h>

// ---------------- problem constants ----------------
#define HID     2048
#define BATCHN  64
#define G4      8192
#define NSTEPS  30
#define NTILE   128           // M tiles of 64 gate-rows -> 128 CTAs
#define NKCH    32            // K chunks of 64 fp16 (128B rows, SW128)
#define WCH     8192          // bytes per W chunk tile (64 rows x 128B)
#define HCH     8192          // bytes per h chunk tile (64 batch x 128B)
#define NITER   16            // 2 chunks per iteration
#define STG     32768         // stage = 2 x (W 8K + h 8K)
#define NSTG    4
#define SMEM_REQ (NSTG*STG + 1024)

// ---------------- device scratch (static, no allocs) ----------------
__device__ __align__(1024) unsigned char g_wsum[NTILE*NKCH*WCH]; // 32MB fp16 (Wih+Whh)
__device__ __align__(1024) unsigned char g_whh [NTILE*NKCH*WCH]; // 32MB fp16 (Whh, step 0)
__device__ __align__(1024) unsigned char g_hA[NKCH*HCH];         // 256KB tiled fp16 h
__device__ __align__(1024) unsigned char g_hB[NKCH*HCH];
__device__ float g_c[BATCHN*HID];
__device__ float g_bias[G4];

// ---------------- helpers ----------------
__device__ __forceinline__ uint32_t smem_u32(const void* p) {
    uint32_t a;
    asm("{ .reg .u64 t; cvta.to.shared.u64 t, %1; cvt.u32.u64 %0, t; }" : "=r"(a) : "l"(p));
    return a;
}
__device__ __forceinline__ uint32_t swz(uint32_t o) { return o ^ ((o >> 3) & 0x70); }

__device__ __forceinline__ void ldm4(uint32_t* r, uint32_t a) {
    asm volatile("ldmatrix.sync.aligned.m8n8.x4.shared.b16 {%0,%1,%2,%3}, [%4];"
                 : "=r"(r[0]), "=r"(r[1]), "=r"(r[2]), "=r"(r[3]) : "r"(a));
}
__device__ __forceinline__ void mma16816(float* d, const uint32_t* a, uint32_t b0, uint32_t b1) {
    asm volatile("mma.sync.aligned.m16n8k16.row.col.f32.f16.f16.f32 "
                 "{%0,%1,%2,%3}, {%4,%5,%6,%7}, {%8,%9}, {%0,%1,%2,%3};"
                 : "+f"(d[0]), "+f"(d[1]), "+f"(d[2]), "+f"(d[3])
                 : "r"(a[0]), "r"(a[1]), "r"(a[2]), "r"(a[3]), "r"(b0), "r"(b1));
}
__device__ __forceinline__ void cp16(uint32_t dst, const void* src) {
    asm volatile("cp.async.cg.shared.global [%0], [%1], 16;" :: "r"(dst), "l"(src) : "memory");
}
#define CP_COMMIT() asm volatile("cp.async.commit_group;" ::: "memory")
__device__ __forceinline__ float sigm(float x) {
    x = fminf(15.f, fmaxf(-15.f, x));
    return 1.f / (1.f + __expf(-x));
}
__device__ __forceinline__ float tanh_(float x) {
    x = fminf(8.f, fmaxf(-8.f, x));
    float e = __expf(-2.f * x);
    return (1.f - e) / (1.f + e);
}

// ---------------- prep: tiled + SW128-swizzled fp16 weights ----------------
// Tile t (0..127), row r (0..63): gate = r>>4, unit = r&15 -> orig row gate*HID + t*16 + unit.
__global__ void prep_weights(const float* __restrict__ Wih, const float* __restrict__ Whh) {
    int id  = blockIdx.x * 256 + threadIdx.x;     // 8,388,608 (one half2 each)
    int cp  = id & 31;
    int row = (id >> 5) & 63;
    int kc  = (id >> 11) & 31;
    int t   = id >> 16;
    int gate = row >> 4, u = row & 15;
    long orow = (long)gate * HID + t * 16 + u;
    int  ocol = kc * 64 + cp * 2;
    float2 wi = *(const float2*)(Wih + orow * HID + ocol);
    float2 wh = *(const float2*)(Whh + orow * HID + ocol);
    uint32_t toff = (uint32_t)(t * NKCH + kc) * WCH + swz((uint32_t)(row * 128 + cp * 4));
    *(__half2*)(g_wsum + toff) =
        __halves2half2(__float2half_rn(wi.x + wh.x), __float2half_rn(wi.y + wh.y));
    *(__half2*)(g_whh + toff) =
        __halves2half2(__float2half_rn(wh.x), __float2half_rn(wh.y));
}

// zero c, fused bias, tiled fp16 h0, out initialized to b_out
__global__ void prep_misc(const float* __restrict__ tok,
                          const float* __restrict__ bih, const float* __restrict__ bhh,
                          const float* __restrict__ bout, float* __restrict__ out) {
    int id = blockIdx.x * 256 + threadIdx.x;      // 131072
    float h0 = tok[id];
    g_c[id] = 0.0f;
    int b = id >> 11, hid = id & 2047;
    int kc = hid >> 6, cc = hid & 63;
    uint32_t off = (uint32_t)kc * HCH + swz((uint32_t)(b * 128 + cc * 2));
    *(__half*)(g_hA + off) = __float2half_rn(h0);
    if (id < G4) g_bias[id] = bih[id] + bhh[id];
    if (id < BATCHN * NSTEPS) out[id] = bout[0];
}

// ---------------- one LSTM step ----------------
// 512 threads, warp grid 2M x 2N x 4K; 2 chunks per iteration, 4 stages in flight.
#define SMX(g, b, u) smx[((g) * 64 + (b)) * 17 + (u)]

__global__ void __launch_bounds__(512, 1) lstm_step(int step, const float* __restrict__ Wout,
                                                    float* __restrict__ out) {
    extern __shared__ unsigned char smraw[];
    uint32_t sbr  = smem_u32(smraw);
    uint32_t base = (sbr + 1023) & ~1023u;
    float* smx = (float*)(smraw + (base - sbr));   // epilogue scratch, overlaps stage 0

    int tid = threadIdx.x;
    int lane = tid & 31, wid = tid >> 5;
    int kw     = wid & 3;
    int warp_m = (wid >> 2) & 1;
    int warp_n = wid >> 3;
    int blk = blockIdx.x;

    const unsigned char* wsrc = ((step ? g_wsum : g_whh) + (size_t)blk * NKCH * WCH);
    const unsigned char* hsrc = (step & 1) ? g_hB : g_hA;
    unsigned char*       hout = (step & 1) ? g_hA : g_hB;

    float wout = Wout[blk * 16 + (tid & 15)];

    // ldmatrix lane address components (k16 slice at byte offset kw*32)
    uint32_t kof    = (uint32_t)kw * 32;
    uint32_t a_colb = (uint32_t)((lane >> 4) << 4);
    uint32_t a_r0   = (uint32_t)(warp_m * 32 + (lane & 15));
    uint32_t b_row  = (uint32_t)(warp_n * 32 + (lane & 7) + ((lane >> 4) << 3));
    uint32_t b_colb = (uint32_t)(((lane >> 3) & 1) << 4);

    float acc[2][16];
    #pragma unroll
    for (int i = 0; i < 2; i++)
        #pragma unroll
        for (int j = 0; j < 16; j++) acc[i][j] = 0.f;

    int o = tid * 16;

    // prefetch stages 0..2 (chunks 0..5)
    #pragma unroll
    for (int s = 0; s < 3; s++) {
        uint32_t sb = base + (uint32_t)s * STG;
        size_t gw = (size_t)(2 * s) * WCH;
        size_t gh = (size_t)(2 * s) * HCH;
        cp16(sb + o,         wsrc + gw + o);
        cp16(sb + 8192 + o,  hsrc + gh + o);
        cp16(sb + 16384 + o, wsrc + gw + WCH + o);
        cp16(sb + 24576 + o, hsrc + gh + HCH + o);
        CP_COMMIT();
    }

    for (int kp = 0; kp < NITER; kp++) {
        if (kp < NITER - 2)       asm volatile("cp.async.wait_group 2;" ::: "memory");
        else if (kp == NITER - 2) asm volatile("cp.async.wait_group 1;" ::: "memory");
        else                      asm volatile("cp.async.wait_group 0;" ::: "memory");
        __syncthreads();

        int np = kp + 3;
        if (np < NITER) {
            uint32_t sb = base + (uint32_t)(np & 3) * STG;
            size_t gw = (size_t)(2 * np) * WCH;
            size_t gh = (size_t)(2 * np) * HCH;
            cp16(sb + o,         wsrc + gw + o);
            cp16(sb + 8192 + o,  hsrc + gh + o);
            cp16(sb + 16384 + o, wsrc + gw + WCH + o);
            cp16(sb + 24576 + o, hsrc + gh + HCH + o);
            CP_COMMIT();
        }

        uint32_t sb = base + (uint32_t)(kp & 3) * STG;
        uint32_t fa0[2][4], fa1[2][4], fb0[2][4], fb1[2][4];
        #pragma unroll
        for (int c = 0; c < 2; c++) {
            uint32_t sw = sb + (uint32_t)c * 16384;
            uint32_t sh = sw + 8192;
            ldm4(fa0[c], sw + swz(a_r0 * 128 + kof + a_colb));
            ldm4(fa1[c], sw + swz((a_r0 + 16) * 128 + kof + a_colb));
            ldm4(fb0[c], sh + swz(b_row * 128 + kof + b_colb));
            ldm4(fb1[c], sh + swz((b_row + 16) * 128 + kof + b_colb));
        }
        #pragma unroll
        for (int c = 0; c < 2; c++) {
            mma16816(acc[0] + 0,  fa0[c], fb0[c][0], fb0[c][1]);
            mma16816(acc[0] + 4,  fa0[c], fb0[c][2], fb0[c][3]);
            mma16816(acc[0] + 8,  fa0[c], fb1[c][0], fb1[c][1]);
            mma16816(acc[0] + 12, fa0[c], fb1[c][2], fb1[c][3]);
            mma16816(acc[1] + 0,  fa1[c], fb0[c][0], fb0[c][1]);
            mma16816(acc[1] + 4,  fa1[c], fb0[c][2], fb0[c][3]);
            mma16816(acc[1] + 8,  fa1[c], fb1[c][0], fb1[c][1]);
            mma16816(acc[1] + 12, fa1[c], fb1[c][2], fb1[c][3]);
        }
    }
    __syncthreads();

    // ---- K-group reduction into smx[gate][batch][unit] (4 sequential rounds) ----
    #pragma unroll
    for (int r = 0; r < 4; r++) {
        if (kw == r) {
            #pragma unroll
            for (int mt = 0; mt < 2; mt++) {
                int gate = warp_m * 2 + mt;
                #pragma unroll
                for (int g = 0; g < 4; g++) {
                    int n0 = warp_n * 32 + 8 * g + 2 * (lane & 3);
                    int u0 = lane >> 2;
                    if (r == 0) {
                        SMX(gate, n0,     u0    ) = acc[mt][4 * g + 0];
                        SMX(gate, n0 + 1, u0    ) = acc[mt][4 * g + 1];
                        SMX(gate, n0,     u0 + 8) = acc[mt][4 * g + 2];
                        SMX(gate, n0 + 1, u0 + 8) = acc[mt][4 * g + 3];
                    } else {
                        SMX(gate, n0,     u0    ) += acc[mt][4 * g + 0];
                        SMX(gate, n0 + 1, u0    ) += acc[mt][4 * g + 1];
                        SMX(gate, n0,     u0 + 8) += acc[mt][4 * g + 2];
                        SMX(gate, n0 + 1, u0 + 8) += acc[mt][4 * g + 3];
                    }
                }
            }
        }
        __syncthreads();
    }

    // ---- fused LSTM cell + output projection: 16 units x 64 batch per CTA ----
    int kcb = blk >> 2;
    #pragma unroll
    for (int k = 0; k < 2; k++) {
        int p = k * 512 + tid;          // (unit, batch); u = tid&15 constant
        int u = p & 15, b = p >> 4;
        int hid = blk * 16 + u;
        float xi = SMX(0, b, u) + g_bias[hid];
        float xf = SMX(1, b, u) + g_bias[2048 + hid];
        float xg = SMX(2, b, u) + g_bias[4096 + hid];
        float xo = SMX(3, b, u) + g_bias[6144 + hid];
        float ii = sigm(xi), ff = sigm(xf), gg = tanh_(xg), oo = sigm(xo);
        int ci = b * HID + hid;
        float c = ff * g_c[ci] + ii * gg;
        g_c[ci] = c;
        float h = oo * tanh_(c);
        uint32_t off = (uint32_t)kcb * HCH +
                       swz((uint32_t)(b * 128 + ((blk & 3) * 16 + u) * 2));
        *(__half*)(hout + off) = __float2half_rn(h);
        // y partial: sum h*wout over the 16 units in this half-warp group
        float part = h * wout;
        #pragma unroll
        for (int s = 8; s; s >>= 1)
            part += __shfl_xor_sync(0xFFFFFFFFu, part, s);
        if ((lane & 15) == 0)
            atomicAdd(out + b * NSTEPS + step, part);
    }
}

// ---------------- launch ----------------
extern "C" void kernel_launch(void* const* d_in, const int* in_sizes, int n_in,
                              void* d_out, int out_size) {
    int wi = (n_in >= 8) ? 2 : 1;   // skip scalar `steps` input if present
    const float* tok  = (const float*)d_in[0];
    const float* Wih  = (const float*)d_in[wi];
    const float* Whh  = (const float*)d_in[wi + 1];
    const float* bih  = (const float*)d_in[wi + 2];
    const float* bhh  = (const float*)d_in[wi + 3];
    const float* Wout = (const float*)d_in[wi + 4];
    const float* bout = (const float*)d_in[wi + 5];
    float* out = (float*)d_out;

    cudaFuncSetAttribute(lstm_step, cudaFuncAttributeMaxDynamicSharedMemorySize, SMEM_REQ);

    prep_weights<<<32768, 256>>>(Wih, Whh);
    prep_misc<<<512, 256>>>(tok, bih, bhh, bout, out);
    for (int t = 0; t < NSTEPS; t++)
        lstm_step<<<NTILE, 512, SMEM_REQ>>>(t, Wout, out);
}

// round 14
// speedup vs baseline: 1.0444x; 1.0064x over previous
#include <cuda_runtime.h>
#include <cuda_fp16.h>
#include <stdint.h>

// ---------------- problem constants ----------------
#define HID     2048
#define BATCHN  64
#define G4      8192
#define NSTEPS  30
#define NTILE   128           // M tiles of 64 gate-rows -> 128 CTAs
#define NKCH    32            // K chunks of 64 fp16
#define WFCH    8192          // bytes per W fragment-major chunk (64x64 fp16)
#define HCH     8192          // bytes per h chunk tile (64 batch x 128B, SW128)
#define NITER   16            // 2 chunks per iteration
#define HSTG    16384         // h stage = 2 chunks x 8K
#define NSTG    4
#define SMX_BYTES (4*64*17*4) // 17408
#define SMEM_REQ (NSTG*HSTG + SMX_BYTES + 1024)

// ---------------- device scratch (static, no allocs) ----------------
__device__ __align__(1024) unsigned char g_wsumF[NTILE*NKCH*WFCH]; // 32MB fragment-major W_ih+W_hh
__device__ __align__(1024) unsigned char g_whhF [NTILE*NKCH*WFCH]; // 32MB fragment-major W_hh
__device__ __align__(1024) unsigned char g_hA[NKCH*HCH];           // 256KB tiled fp16 h
__device__ __align__(1024) unsigned char g_hB[NKCH*HCH];
__device__ float g_c[BATCHN*HID];
__device__ float g_bias[G4];

// ---------------- helpers ----------------
__device__ __forceinline__ uint32_t smem_u32(const void* p) {
    uint32_t a;
    asm("{ .reg .u64 t; cvta.to.shared.u64 t, %1; cvt.u32.u64 %0, t; }" : "=r"(a) : "l"(p));
    return a;
}
__device__ __forceinline__ uint32_t swz(uint32_t o) { return o ^ ((o >> 3) & 0x70); }

__device__ __forceinline__ void ldm4(uint32_t* r, uint32_t a) {
    asm volatile("ldmatrix.sync.aligned.m8n8.x4.shared.b16 {%0,%1,%2,%3}, [%4];"
                 : "=r"(r[0]), "=r"(r[1]), "=r"(r[2]), "=r"(r[3]) : "r"(a));
}
__device__ __forceinline__ void mma16816(float* d, const uint32_t* a, uint32_t b0, uint32_t b1) {
    asm volatile("mma.sync.aligned.m16n8k16.row.col.f32.f16.f16.f32 "
                 "{%0,%1,%2,%3}, {%4,%5,%6,%7}, {%8,%9}, {%0,%1,%2,%3};"
                 : "+f"(d[0]), "+f"(d[1]), "+f"(d[2]), "+f"(d[3])
                 : "r"(a[0]), "r"(a[1]), "r"(a[2]), "r"(a[3]), "r"(b0), "r"(b1));
}
__device__ __forceinline__ void cp16(uint32_t dst, const void* src) {
    asm volatile("cp.async.cg.shared.global [%0], [%1], 16;" :: "r"(dst), "l"(src) : "memory");
}
#define CP_COMMIT() asm volatile("cp.async.commit_group;" ::: "memory")
__device__ __forceinline__ float sigm(float x) {
    x = fminf(15.f, fmaxf(-15.f, x));
    return 1.f / (1.f + __expf(-x));
}
__device__ __forceinline__ float tanh_(float x) {
    x = fminf(8.f, fmaxf(-8.f, x));
    float e = __expf(-2.f * x);
    return (1.f - e) / (1.f + e);
}

// ---------------- prep: fragment-major fp16 weights ----------------
// For tile blk, chunk kc: logical A tile rows r (0..63): gate = r>>4, unit = r&15,
// orig row = gate*HID + blk*16 + unit; cols = kc*64 .. +63.
// Fragment unit (kw, wm, f, lane) 16B = mma m16n8k16 A regs a0..a3 for
// rows R0 = wm*32+f*16+(lane>>2), R0+8; cols C0 = kw*16+2*(lane&3), +1, +8, +9.
__global__ void prep_weights(const float* __restrict__ Wih, const float* __restrict__ Whh) {
    __shared__ __half s_sum[64][66];
    __shared__ __half s_hh [64][66];
    int blk = blockIdx.x >> 5;
    int kc  = blockIdx.x & 31;
    int tid = threadIdx.x;

    int r = tid >> 2;
    int cb = (tid & 3) * 4;
    int gate = r >> 4, u = r & 15;
    long orow = (long)gate * HID + blk * 16 + u;
    const float* pi = Wih + orow * HID + kc * 64;
    const float* ph = Whh + orow * HID + kc * 64;
    #pragma unroll
    for (int j = 0; j < 4; j++) {
        int c = cb + j * 16;
        float4 a = *(const float4*)(pi + c);
        float4 b = *(const float4*)(ph + c);
        s_sum[r][c + 0] = __float2half_rn(a.x + b.x);
        s_sum[r][c + 1] = __float2half_rn(a.y + b.y);
        s_sum[r][c + 2] = __float2half_rn(a.z + b.z);
        s_sum[r][c + 3] = __float2half_rn(a.w + b.w);
        s_hh[r][c + 0] = __float2half_rn(b.x);
        s_hh[r][c + 1] = __float2half_rn(b.y);
        s_hh[r][c + 2] = __float2half_rn(b.z);
        s_hh[r][c + 3] = __float2half_rn(b.w);
    }
    __syncthreads();

    size_t chbase = (size_t)(blk * NKCH + kc) * 512;   // in 16B units
    #pragma unroll
    for (int it = 0; it < 2; it++) {
        int unit = it * 256 + tid;          // 0..511
        int kw   = unit >> 7;
        int wm   = (unit >> 6) & 1;
        int f    = (unit >> 5) & 1;
        int lane = unit & 31;
        int g = lane >> 2, t = lane & 3;
        int R0 = wm * 32 + f * 16 + g;
        int C0 = kw * 16 + 2 * t;
        uint4 vs, vh;
        vs.x = *(const uint32_t*)&s_sum[R0][C0];
        vs.y = *(const uint32_t*)&s_sum[R0 + 8][C0];
        vs.z = *(const uint32_t*)&s_sum[R0][C0 + 8];
        vs.w = *(const uint32_t*)&s_sum[R0 + 8][C0 + 8];
        vh.x = *(const uint32_t*)&s_hh[R0][C0];
        vh.y = *(const uint32_t*)&s_hh[R0 + 8][C0];
        vh.z = *(const uint32_t*)&s_hh[R0][C0 + 8];
        vh.w = *(const uint32_t*)&s_hh[R0 + 8][C0 + 8];
        ((uint4*)g_wsumF)[chbase + unit] = vs;
        ((uint4*)g_whhF)[chbase + unit]  = vh;
    }
}

// zero c, fused bias, tiled fp16 h0, out initialized to b_out
__global__ void prep_misc(const float* __restrict__ tok,
                          const float* __restrict__ bih, const float* __restrict__ bhh,
                          const float* __restrict__ bout, float* __restrict__ out) {
    int id = blockIdx.x * 256 + threadIdx.x;      // 131072
    float h0 = tok[id];
    g_c[id] = 0.0f;
    int b = id >> 11, hid = id & 2047;
    int kc = hid >> 6, cc = hid & 63;
    uint32_t off = (uint32_t)kc * HCH + swz((uint32_t)(b * 128 + cc * 2));
    *(__half*)(g_hA + off) = __float2half_rn(h0);
    if (id < G4) g_bias[id] = bih[id] + bhh[id];
    if (id < BATCHN * NSTEPS) out[id] = bout[0];
}

// ---------------- one LSTM step ----------------
// 512 threads, warp grid 2M x 2N x 4K; W via direct LDG.128 (fragment-major),
// h via cp.async + ldmatrix (4 stages, 2 chunks each).
#define SMX(g, b, u) smx[((g) * 64 + (b)) * 17 + (u)]

__global__ void __launch_bounds__(512, 1) lstm_step(int step, const float* __restrict__ Wout,
                                                    float* __restrict__ out) {
    extern __shared__ unsigned char smraw[];
    uint32_t sbr  = smem_u32(smraw);
    uint32_t base = (sbr + 1023) & ~1023u;
    float* smx = (float*)(smraw + (base - sbr) + NSTG * HSTG);

    int tid = threadIdx.x;
    int lane = tid & 31, wid = tid >> 5;
    int kw     = wid & 3;
    int warp_m = (wid >> 2) & 1;
    int warp_n = wid >> 3;
    int blk = blockIdx.x;

    const unsigned char* wf = ((step ? g_wsumF : g_whhF) + (size_t)blk * NKCH * WFCH);
    const unsigned char* hsrc = (step & 1) ? g_hB : g_hA;
    unsigned char*       hout = (step & 1) ? g_hA : g_hB;

    float wout = Wout[blk * 16 + (tid & 15)];

    // W fragment base offset within a chunk for this (kw, warp_m, lane)
    uint32_t wb = (uint32_t)kw * 2048 + (uint32_t)warp_m * 1024 + (uint32_t)lane * 16;

    // h ldmatrix lane address components
    uint32_t kof    = (uint32_t)kw * 32;
    uint32_t b_row  = (uint32_t)(warp_n * 32 + (lane & 7) + ((lane >> 4) << 3));
    uint32_t b_colb = (uint32_t)(((lane >> 3) & 1) << 4);

    float acc[2][16];
    #pragma unroll
    for (int i = 0; i < 2; i++)
        #pragma unroll
        for (int j = 0; j < 16; j++) acc[i][j] = 0.f;

    int o = tid * 16;

    // prefetch h stages 0..2 (chunks 0..5)
    #pragma unroll
    for (int s = 0; s < 3; s++) {
        uint32_t sb = base + (uint32_t)s * HSTG;
        size_t gh = (size_t)(2 * s) * HCH;
        cp16(sb + o,        hsrc + gh + o);
        cp16(sb + 8192 + o, hsrc + gh + HCH + o);
        CP_COMMIT();
    }

    // W fragments for iteration 0 (chunks 0,1)
    uint4 wc0, wc1, wc2, wc3;
    {
        const unsigned char* p0 = wf + wb;
        const unsigned char* p1 = wf + WFCH + wb;
        wc0 = *(const uint4*)(p0);
        wc1 = *(const uint4*)(p0 + 512);
        wc2 = *(const uint4*)(p1);
        wc3 = *(const uint4*)(p1 + 512);
    }

    for (int kp = 0; kp < NITER; kp++) {
        // issue next-iteration W fragment loads (distance 1; L2-hit latency covered)
        uint4 wn0, wn1, wn2, wn3;
        if (kp + 1 < NITER) {
            const unsigned char* p0 = wf + (size_t)(2 * (kp + 1)) * WFCH + wb;
            wn0 = *(const uint4*)(p0);
            wn1 = *(const uint4*)(p0 + 512);
            wn2 = *(const uint4*)(p0 + WFCH);
            wn3 = *(const uint4*)(p0 + WFCH + 512);
        }

        if (kp < NITER - 2)       asm volatile("cp.async.wait_group 2;" ::: "memory");
        else if (kp == NITER - 2) asm volatile("cp.async.wait_group 1;" ::: "memory");
        else                      asm volatile("cp.async.wait_group 0;" ::: "memory");
        __syncthreads();

        int np = kp + 3;
        if (np < NITER) {
            uint32_t sb = base + (uint32_t)(np & 3) * HSTG;
            size_t gh = (size_t)(2 * np) * HCH;
            cp16(sb + o,        hsrc + gh + o);
            cp16(sb + 8192 + o, hsrc + gh + HCH + o);
            CP_COMMIT();
        }

        uint32_t sb = base + (uint32_t)(kp & 3) * HSTG;
        uint32_t fb0[2][4], fb1[2][4];
        #pragma unroll
        for (int c = 0; c < 2; c++) {
            uint32_t sh = sb + (uint32_t)c * 8192;
            ldm4(fb0[c], sh + swz(b_row * 128 + kof + b_colb));
            ldm4(fb1[c], sh + swz((b_row + 16) * 128 + kof + b_colb));
        }
        const uint32_t* a00 = (const uint32_t*)&wc0;   // chunk0 frag0 (rows m0..15 of warp half)
        const uint32_t* a01 = (const uint32_t*)&wc1;   // chunk0 frag1 (rows m16..31)
        const uint32_t* a10 = (const uint32_t*)&wc2;   // chunk1 frag0
        const uint32_t* a11 = (const uint32_t*)&wc3;   // chunk1 frag1
        mma16816(acc[0] + 0,  a00, fb0[0][0], fb0[0][1]);
        mma16816(acc[0] + 4,  a00, fb0[0][2], fb0[0][3]);
        mma16816(acc[0] + 8,  a00, fb1[0][0], fb1[0][1]);
        mma16816(acc[0] + 12, a00, fb1[0][2], fb1[0][3]);
        mma16816(acc[1] + 0,  a01, fb0[0][0], fb0[0][1]);
        mma16816(acc[1] + 4,  a01, fb0[0][2], fb0[0][3]);
        mma16816(acc[1] + 8,  a01, fb1[0][0], fb1[0][1]);
        mma16816(acc[1] + 12, a01, fb1[0][2], fb1[0][3]);
        mma16816(acc[0] + 0,  a10, fb0[1][0], fb0[1][1]);
        mma16816(acc[0] + 4,  a10, fb0[1][2], fb0[1][3]);
        mma16816(acc[0] + 8,  a10, fb1[1][0], fb1[1][1]);
        mma16816(acc[0] + 12, a10, fb1[1][2], fb1[1][3]);
        mma16816(acc[1] + 0,  a11, fb0[1][0], fb0[1][1]);
        mma16816(acc[1] + 4,  a11, fb0[1][2], fb0[1][3]);
        mma16816(acc[1] + 8,  a11, fb1[1][0], fb1[1][1]);
        mma16816(acc[1] + 12, a11, fb1[1][2], fb1[1][3]);

        wc0 = wn0; wc1 = wn1; wc2 = wn2; wc3 = wn3;
    }
    __syncthreads();

    // ---- K-group reduction into smx[gate][batch][unit] (4 sequential rounds) ----
    #pragma unroll
    for (int r = 0; r < 4; r++) {
        if (kw == r) {
            #pragma unroll
            for (int mt = 0; mt < 2; mt++) {
                int gate = warp_m * 2 + mt;
                #pragma unroll
                for (int g = 0; g < 4; g++) {
                    int n0 = warp_n * 32 + 8 * g + 2 * (lane & 3);
                    int u0 = lane >> 2;
                    if (r == 0) {
                        SMX(gate, n0,     u0    ) = acc[mt][4 * g + 0];
                        SMX(gate, n0 + 1, u0    ) = acc[mt][4 * g + 1];
                        SMX(gate, n0,     u0 + 8) = acc[mt][4 * g + 2];
                        SMX(gate, n0 + 1, u0 + 8) = acc[mt][4 * g + 3];
                    } else {
                        SMX(gate, n0,     u0    ) += acc[mt][4 * g + 0];
                        SMX(gate, n0 + 1, u0    ) += acc[mt][4 * g + 1];
                        SMX(gate, n0,     u0 + 8) += acc[mt][4 * g + 2];
                        SMX(gate, n0 + 1, u0 + 8) += acc[mt][4 * g + 3];
                    }
                }
            }
        }
        __syncthreads();
    }

    // ---- fused LSTM cell + output projection: 16 units x 64 batch per CTA ----
    int kcb = blk >> 2;
    #pragma unroll
    for (int k = 0; k < 2; k++) {
        int p = k * 512 + tid;          // (unit, batch); u = tid&15 constant
        int u = p & 15, b = p >> 4;
        int hid = blk * 16 + u;
        float xi = SMX(0, b, u) + g_bias[hid];
        float xf = SMX(1, b, u) + g_bias[2048 + hid];
        float xg = SMX(2, b, u) + g_bias[4096 + hid];
        float xo = SMX(3, b, u) + g_bias[6144 + hid];
        float ii = sigm(xi), ff = sigm(xf), gg = tanh_(xg), oo = sigm(xo);
        int ci = b * HID + hid;
        float c = ff * g_c[ci] + ii * gg;
        g_c[ci] = c;
        float h = oo * tanh_(c);
        uint32_t off = (uint32_t)kcb * HCH +
                       swz((uint32_t)(b * 128 + ((blk & 3) * 16 + u) * 2));
        *(__half*)(hout + off) = __float2half_rn(h);
        float part = h * wout;
        #pragma unroll
        for (int s = 8; s; s >>= 1)
            part += __shfl_xor_sync(0xFFFFFFFFu, part, s);
        if ((lane & 15) == 0)
            atomicAdd(out + b * NSTEPS + step, part);
    }
}

// ---------------- launch ----------------
extern "C" void kernel_launch(void* const* d_in, const int* in_sizes, int n_in,
                              void* d_out, int out_size) {
    int wi = (n_in >= 8) ? 2 : 1;   // skip scalar `steps` input if present
    const float* tok  = (const float*)d_in[0];
    const float* Wih  = (const float*)d_in[wi];
    const float* Whh  = (const float*)d_in[wi + 1];
    const float* bih  = (const float*)d_in[wi + 2];
    const float* bhh  = (const float*)d_in[wi + 3];
    const float* Wout = (const float*)d_in[wi + 4];
    const float* bout = (const float*)d_in[wi + 5];
    float* out = (float*)d_out;

    cudaFuncSetAttribute(lstm_step, cudaFuncAttributeMaxDynamicSharedMemorySize, SMEM_REQ);

    prep_weights<<<NTILE * NKCH, 256>>>(Wih, Whh);
    prep_misc<<<512, 256>>>(tok, bih, bhh, bout, out);
    for (int t = 0; t < NSTEPS; t++)
        lstm_step<<<NTILE, 512, SMEM_REQ>>>(t, Wout, out);
}